// round 2
// baseline (speedup 1.0000x reference)
#include <cuda_runtime.h>
#include <math.h>

// Problem constants
#define B_   8
#define S_   8192
#define D_   1024
#define H_   16
#define GS_  16
#define K_   64
#define HD_  64
#define G_   512            // S/GS groups per batch
#define F_   256            // DH4 scorer hidden
#define BG_  (B_*G_)        // 4096
#define BK_  (B_*K_)        // 512

// ---------------- scratch (static __device__, no allocation) ----------------
__device__ float g_groups[BG_*D_];   // 16 MB group means
__device__ float g_h[BG_*F_];        // 4 MB scorer hidden (pre-bias)
__device__ float g_scores[BG_];
__device__ int   g_topidx[BK_];
__device__ int   g_selmap[BG_];      // group -> slot or -1
__device__ float g_sel[BK_*D_];
__device__ float g_q[BK_*D_];
__device__ float g_k[BK_*D_];
__device__ float g_v[BK_*D_];
__device__ float g_ctx[BK_*D_];
__device__ float g_outg[BK_*D_];

// ---------------- 1. group mean pool ----------------
// grid BG_, 256 threads; each thread owns one float4 of the 1024-dim row.
__global__ void pool_kernel(const float* __restrict__ hs) {
    int bg = blockIdx.x;                 // b*512+g
    int b = bg >> 9, g = bg & 511;
    const float* base = hs + (b*S_ + g*GS_) * D_;
    int d4 = threadIdx.x * 4;
    float4 acc = make_float4(0.f, 0.f, 0.f, 0.f);
#pragma unroll
    for (int r = 0; r < GS_; r++) {
        float4 v = *(const float4*)(base + r*D_ + d4);
        acc.x += v.x; acc.y += v.y; acc.z += v.z; acc.w += v.w;
    }
    const float inv = 1.0f / (float)GS_;
    acc.x *= inv; acc.y *= inv; acc.z *= inv; acc.w *= inv;
    *(float4*)(g_groups + bg*D_ + d4) = acc;
}

// ---------------- generic fp32 SGEMM: C[M,N] = A[M,K] @ B[K,N] ----------------
// 64x64 block tile, K-chunk 16, 256 threads, 4x4 per-thread microtile.
// M,N multiples of 64; K multiple of 16.
__global__ void sgemm64(const float* __restrict__ A, const float* __restrict__ Bm,
                        float* __restrict__ C, int M, int N, int Kd) {
    __shared__ float As[16][64];
    __shared__ float Bs[16][64];
    int m0 = blockIdx.y * 64;
    int n0 = blockIdx.x * 64;
    int tid = threadIdx.x;
    int tx = tid & 15, ty = tid >> 4;

    int rowA = tid >> 2;               // 0..63
    int kqA  = (tid & 3) << 2;         // 0,4,8,12
    int rowB = tid >> 4;               // 0..15
    int colB = (tid & 15) << 2;        // 0..60

    float acc[4][4];
#pragma unroll
    for (int i = 0; i < 4; i++)
#pragma unroll
        for (int j = 0; j < 4; j++) acc[i][j] = 0.f;

    for (int k0 = 0; k0 < Kd; k0 += 16) {
        float4 av = *(const float4*)(A + (m0 + rowA)*Kd + k0 + kqA);
        As[kqA+0][rowA] = av.x; As[kqA+1][rowA] = av.y;
        As[kqA+2][rowA] = av.z; As[kqA+3][rowA] = av.w;
        float4 bv = *(const float4*)(Bm + (k0 + rowB)*N + n0 + colB);
        *(float4*)(&Bs[rowB][colB]) = bv;
        __syncthreads();
#pragma unroll
        for (int kk = 0; kk < 16; kk++) {
            float4 a = *(const float4*)(&As[kk][ty << 2]);
            float4 b = *(const float4*)(&Bs[kk][tx << 2]);
            float ar0 = a.x, ar1 = a.y, ar2 = a.z, ar3 = a.w;
            acc[0][0] += ar0 * b.x; acc[0][1] += ar0 * b.y;
            acc[0][2] += ar0 * b.z; acc[0][3] += ar0 * b.w;
            acc[1][0] += ar1 * b.x; acc[1][1] += ar1 * b.y;
            acc[1][2] += ar1 * b.z; acc[1][3] += ar1 * b.w;
            acc[2][0] += ar2 * b.x; acc[2][1] += ar2 * b.y;
            acc[2][2] += ar2 * b.z; acc[2][3] += ar2 * b.w;
            acc[3][0] += ar3 * b.x; acc[3][1] += ar3 * b.y;
            acc[3][2] += ar3 * b.z; acc[3][3] += ar3 * b.w;
        }
        __syncthreads();
    }
#pragma unroll
    for (int i = 0; i < 4; i++) {
        float4 v = make_float4(acc[i][0], acc[i][1], acc[i][2], acc[i][3]);
        *(float4*)(C + (m0 + (ty<<2) + i)*N + n0 + (tx<<2)) = v;
    }
}

// ---------------- 2b. scorer epilogue: bias -> relu -> dot Ws2 ----------------
// grid 512, 256 threads (8 warps -> 8 groups per block)
__global__ void score_reduce(const float* __restrict__ bs1,
                             const float* __restrict__ Ws2,
                             const float* __restrict__ bs2) {
    int g = blockIdx.x * 8 + (threadIdx.x >> 5);
    int lane = threadIdx.x & 31;
    float s = 0.f;
#pragma unroll
    for (int i = 0; i < 8; i++) {
        int f = lane + i*32;
        float v = g_h[g*F_ + f] + bs1[f];
        s += fmaxf(v, 0.f) * Ws2[f];
    }
#pragma unroll
    for (int o = 16; o; o >>= 1) s += __shfl_xor_sync(0xffffffffu, s, o);
    if (lane == 0) g_scores[g] = s + bs2[0];
}

// ---------------- 3. top-64 per batch (iterative argmax, tie -> lower idx) ----
__global__ void topk_kernel() {
    int b = blockIdx.x;
    int t = threadIdx.x;      // 512
    __shared__ float v[512];
    __shared__ float rv[512];
    __shared__ int   ri[512];
    v[t] = g_scores[b*G_ + t];
    g_selmap[b*G_ + t] = -1;
    __syncthreads();
    for (int it = 0; it < K_; it++) {
        rv[t] = v[t]; ri[t] = t;
        __syncthreads();
        for (int s = 256; s > 0; s >>= 1) {
            if (t < s) {
                float ov = rv[t+s]; int oi = ri[t+s];
                if (ov > rv[t] || (ov == rv[t] && oi < ri[t])) { rv[t] = ov; ri[t] = oi; }
            }
            __syncthreads();
        }
        if (t == 0) {
            int gi = ri[0];
            g_topidx[b*K_ + it] = gi;
            g_selmap[b*G_ + gi] = it;
            v[gi] = -INFINITY;
        }
        __syncthreads();
    }
}

// ---------------- 4. gather selected group rows ----------------
__global__ void gather_kernel() {
    int bk = blockIdx.x;               // b*64+k
    int b = bk >> 6;
    int g = g_topidx[bk];
    int d4 = threadIdx.x * 4;
    *(float4*)(g_sel + bk*D_ + d4) =
        *(const float4*)(g_groups + (b*G_ + g)*D_ + d4);
}

// ---------------- 6. attention per (b, head): 64x64, HD=64 ----------------
__global__ void attn_kernel() {
    int bh = blockIdx.x;
    int b = bh >> 4, h = bh & 15;
    __shared__ float Qs[64][65];   // padded: per-thread row reads conflict-free
    __shared__ float KV[64][64];   // K tile, then reused for V tile
    int t = threadIdx.x;           // 64 threads; thread t = query t
    const float* qbase = g_q + (b*K_)*D_ + h*HD_;
    const float* kbase = g_k + (b*K_)*D_ + h*HD_;
    const float* vbase = g_v + (b*K_)*D_ + h*HD_;
    for (int i = 0; i < 64; i++) {
        Qs[i][t] = qbase[i*D_ + t];
        KV[i][t] = kbase[i*D_ + t];
    }
    __syncthreads();
    float s[64];
#pragma unroll
    for (int j = 0; j < 64; j++) s[j] = 0.f;
    for (int d = 0; d < 64; d++) {
        float qd = Qs[t][d];
#pragma unroll
        for (int j = 0; j < 64; j++) s[j] += qd * KV[j][d];   // KV[j][d] broadcast
    }
    float m = -INFINITY;
#pragma unroll
    for (int j = 0; j < 64; j++) { s[j] *= 0.125f; m = fmaxf(m, s[j]); }
    float sum = 0.f;
#pragma unroll
    for (int j = 0; j < 64; j++) { s[j] = expf(s[j] - m); sum += s[j]; }
    float inv = 1.f / sum;
    __syncthreads();                       // done with K tile
    for (int i = 0; i < 64; i++) KV[i][t] = vbase[i*D_ + t];
    __syncthreads();
    float* outrow = g_ctx + (b*K_ + t)*D_ + h*HD_;
    for (int d = 0; d < 64; d++) {
        float acc = 0.f;
#pragma unroll
        for (int j = 0; j < 64; j++) acc += s[j] * KV[j][d];
        outrow[d] = acc * inv;
    }
}

// ---------------- 8. scatter-broadcast output (covers every element) ----------
// grid BG_, 256 threads: one group -> 16 sequence rows.
__global__ void scatter_kernel(float* __restrict__ out) {
    int bg = blockIdx.x;
    int b = bg >> 9, g = bg & 511;
    int k = g_selmap[bg];
    int d4 = threadIdx.x * 4;
    float4 v = make_float4(0.f, 0.f, 0.f, 0.f);
    if (k >= 0) v = *(const float4*)(g_outg + ((b << 6) + k)*D_ + d4);
    float* dst = out + (b*S_ + g*GS_)*D_ + d4;
#pragma unroll
    for (int r = 0; r < GS_; r++) *(float4*)(dst + r*D_) = v;
}

// ---------------- launch ----------------
extern "C" void kernel_launch(void* const* d_in, const int* in_sizes, int n_in,
                              void* d_out, int out_size) {
    const float* hs  = (const float*)d_in[0];
    const float* Wq  = (const float*)d_in[1];
    const float* Wk  = (const float*)d_in[2];
    const float* Wv  = (const float*)d_in[3];
    const float* Wo  = (const float*)d_in[4];
    const float* Ws1 = (const float*)d_in[5];
    const float* bs1 = (const float*)d_in[6];
    const float* Ws2 = (const float*)d_in[7];
    const float* bs2 = (const float*)d_in[8];
    float* out = (float*)d_out;

    float *p_groups, *p_h, *p_sel, *p_q, *p_k, *p_v, *p_ctx, *p_outg;
    cudaGetSymbolAddress((void**)&p_groups, g_groups);
    cudaGetSymbolAddress((void**)&p_h,      g_h);
    cudaGetSymbolAddress((void**)&p_sel,    g_sel);
    cudaGetSymbolAddress((void**)&p_q,      g_q);
    cudaGetSymbolAddress((void**)&p_k,      g_k);
    cudaGetSymbolAddress((void**)&p_v,      g_v);
    cudaGetSymbolAddress((void**)&p_ctx,    g_ctx);
    cudaGetSymbolAddress((void**)&p_outg,   g_outg);

    pool_kernel<<<BG_, 256>>>(hs);
    // scorer hidden: [4096,1024] @ [1024,256]
    sgemm64<<<dim3(F_/64, BG_/64), 256>>>(p_groups, Ws1, p_h, BG_, F_, D_);
    score_reduce<<<BG_/8, 256>>>(bs1, Ws2, bs2);
    topk_kernel<<<B_, 512>>>();
    gather_kernel<<<BK_, 256>>>();
    // QKV: [512,1024] @ [1024,1024] x3
    sgemm64<<<dim3(D_/64, BK_/64), 256>>>(p_sel, Wq, p_q, BK_, D_, D_);
    sgemm64<<<dim3(D_/64, BK_/64), 256>>>(p_sel, Wk, p_k, BK_, D_, D_);
    sgemm64<<<dim3(D_/64, BK_/64), 256>>>(p_sel, Wv, p_v, BK_, D_, D_);
    attn_kernel<<<B_*H_, 64>>>();
    // Wo: [512,1024] @ [1024,1024]
    sgemm64<<<dim3(D_/64, BK_/64), 256>>>(p_ctx, Wo, p_outg, BK_, D_, D_);
    scatter_kernel<<<BG_, 256>>>(out);
}

// round 3
// speedup vs baseline: 1.6289x; 1.6289x over previous
#include <cuda_runtime.h>
#include <math.h>
#include <stdint.h>

// Problem constants
#define B_   8
#define S_   8192
#define D_   1024
#define H_   16
#define GS_  16
#define K_   64
#define HD_  64
#define G_   512            // S/GS groups per batch
#define F_   256            // DH4 scorer hidden
#define BG_  (B_*G_)        // 4096
#define BK_  (B_*K_)        // 512

// ---------------- scratch (static __device__, no allocation) ----------------
__device__ float g_groups[BG_*D_];
__device__ float g_h[BG_*F_];
__device__ float g_scores[BG_];
__device__ int   g_topidx[BK_];
__device__ int   g_selmap[BG_];
__device__ float g_sel[BK_*D_];
__device__ float g_q[BK_*D_];
__device__ float g_k[BK_*D_];
__device__ float g_v[BK_*D_];
__device__ float g_ctx[BK_*D_];
__device__ float g_outg[BK_*D_];

// ---------------- 1. group mean pool ----------------
__global__ void pool_kernel(const float* __restrict__ hs) {
    int bg = blockIdx.x;
    int b = bg >> 9, g = bg & 511;
    const float* base = hs + (b*S_ + g*GS_) * D_;
    int d4 = threadIdx.x * 4;
    float4 acc = make_float4(0.f, 0.f, 0.f, 0.f);
#pragma unroll
    for (int r = 0; r < GS_; r++) {
        float4 v = *(const float4*)(base + r*D_ + d4);
        acc.x += v.x; acc.y += v.y; acc.z += v.z; acc.w += v.w;
    }
    const float inv = 1.0f / (float)GS_;
    acc.x *= inv; acc.y *= inv; acc.z *= inv; acc.w *= inv;
    *(float4*)(g_groups + bg*D_ + d4) = acc;
}

// ---------------- tf32 helpers ----------------
__device__ __forceinline__ void split_tf32(float x, uint32_t& hi, uint32_t& lo) {
    asm("cvt.rna.tf32.f32 %0, %1;" : "=r"(hi) : "f"(x));
    float r = x - __uint_as_float(hi);
    asm("cvt.rna.tf32.f32 %0, %1;" : "=r"(lo) : "f"(r));
}

__device__ __forceinline__ void mma_tf32(float acc[4], const uint32_t a[4], const uint32_t b[2]) {
    asm volatile(
        "mma.sync.aligned.m16n8k8.row.col.f32.tf32.tf32.f32 "
        "{%0,%1,%2,%3}, {%4,%5,%6,%7}, {%8,%9}, {%0,%1,%2,%3};\n"
        : "+f"(acc[0]), "+f"(acc[1]), "+f"(acc[2]), "+f"(acc[3])
        : "r"(a[0]), "r"(a[1]), "r"(a[2]), "r"(a[3]), "r"(b[0]), "r"(b[1]));
}

// ---------------- tensor-core GEMM: C = A[M,K] @ B[K,N], 3xTF32 ----------------
// 128 threads (4 warps, 2x2), block tile 64x64, K-chunk 32, warp tile 32x32.
// blockIdx.z selects (B,C) pair -> fuses QKV into one launch.
__global__ void gemm_tf32_3x(const float* __restrict__ A,
                             const float* __restrict__ B0,
                             const float* __restrict__ B1,
                             const float* __restrict__ B2,
                             float* __restrict__ C0,
                             float* __restrict__ C1,
                             float* __restrict__ C2,
                             int M, int N, int Kd) {
    const float* Bm = (blockIdx.z == 0) ? B0 : ((blockIdx.z == 1) ? B1 : B2);
    float* C       = (blockIdx.z == 0) ? C0 : ((blockIdx.z == 1) ? C1 : C2);

    __shared__ float As[64][36];   // [m][k], stride 36 -> conflict-free frag loads
    __shared__ float Bs[32][72];   // [k][n], stride 72 -> conflict-free frag loads

    int tid = threadIdx.x;
    int lane = tid & 31, wid = tid >> 5;
    int wm = wid & 1, wn = wid >> 1;          // warp coords in 2x2
    int g = lane >> 2, tig = lane & 3;        // groupID, threadID-in-group

    int m0 = blockIdx.y * 64, n0 = blockIdx.x * 64;

    // global load mapping
    int arow = tid >> 1;                 // 0..63
    int acol = (tid & 1) << 4;           // 0 / 16
    int brow = tid >> 2;                 // 0..31
    int bcol = (tid & 3) << 4;           // 0/16/32/48

    float acc[2][4][4];
#pragma unroll
    for (int sm = 0; sm < 2; sm++)
#pragma unroll
        for (int sn = 0; sn < 4; sn++)
#pragma unroll
            for (int i = 0; i < 4; i++) acc[sm][sn][i] = 0.f;

    for (int k0 = 0; k0 < Kd; k0 += 32) {
#pragma unroll
        for (int i = 0; i < 4; i++) {
            float4 v = *(const float4*)(A + (size_t)(m0 + arow)*Kd + k0 + acol + i*4);
            *(float4*)(&As[arow][acol + i*4]) = v;
        }
#pragma unroll
        for (int i = 0; i < 4; i++) {
            float4 v = *(const float4*)(Bm + (size_t)(k0 + brow)*N + n0 + bcol + i*4);
            *(float4*)(&Bs[brow][bcol + i*4]) = v;
        }
        __syncthreads();

#pragma unroll
        for (int k8 = 0; k8 < 32; k8 += 8) {
            uint32_t ah[2][4], al[2][4];
#pragma unroll
            for (int sm = 0; sm < 2; sm++) {
                int mb = wm*32 + sm*16;
                split_tf32(As[mb + g    ][k8 + tig    ], ah[sm][0], al[sm][0]);
                split_tf32(As[mb + g + 8][k8 + tig    ], ah[sm][1], al[sm][1]);
                split_tf32(As[mb + g    ][k8 + tig + 4], ah[sm][2], al[sm][2]);
                split_tf32(As[mb + g + 8][k8 + tig + 4], ah[sm][3], al[sm][3]);
            }
            uint32_t bh[4][2], bl[4][2];
#pragma unroll
            for (int sn = 0; sn < 4; sn++) {
                int nb = wn*32 + sn*8 + g;
                split_tf32(Bs[k8 + tig    ][nb], bh[sn][0], bl[sn][0]);
                split_tf32(Bs[k8 + tig + 4][nb], bh[sn][1], bl[sn][1]);
            }
#pragma unroll
            for (int sm = 0; sm < 2; sm++)
#pragma unroll
                for (int sn = 0; sn < 4; sn++) {
                    mma_tf32(acc[sm][sn], al[sm], bh[sn]);
                    mma_tf32(acc[sm][sn], ah[sm], bl[sn]);
                    mma_tf32(acc[sm][sn], ah[sm], bh[sn]);
                }
        }
        __syncthreads();
    }

#pragma unroll
    for (int sm = 0; sm < 2; sm++)
#pragma unroll
        for (int sn = 0; sn < 4; sn++) {
            int row = m0 + wm*32 + sm*16 + g;
            int col = n0 + wn*32 + sn*8 + tig*2;
            *(float2*)(C + (size_t)row*N + col)     = make_float2(acc[sm][sn][0], acc[sm][sn][1]);
            *(float2*)(C + (size_t)(row+8)*N + col) = make_float2(acc[sm][sn][2], acc[sm][sn][3]);
        }
}

// ---------------- 2b. scorer epilogue: bias -> relu -> dot Ws2 ----------------
__global__ void score_reduce(const float* __restrict__ bs1,
                             const float* __restrict__ Ws2,
                             const float* __restrict__ bs2) {
    int g = blockIdx.x * 8 + (threadIdx.x >> 5);
    int lane = threadIdx.x & 31;
    float s = 0.f;
#pragma unroll
    for (int i = 0; i < 8; i++) {
        int f = lane + i*32;
        float v = g_h[g*F_ + f] + bs1[f];
        s += fmaxf(v, 0.f) * Ws2[f];
    }
#pragma unroll
    for (int o = 16; o; o >>= 1) s += __shfl_xor_sync(0xffffffffu, s, o);
    if (lane == 0) g_scores[g] = s + bs2[0];
}

// ---------------- 3. top-64 via bitonic sort (desc by score, asc by idx) -----
__global__ void topk_bitonic() {
    int b = blockIdx.x;
    int t = threadIdx.x;    // 512
    __shared__ float sv[512];
    __shared__ int   si[512];
    sv[t] = g_scores[b*G_ + t];
    si[t] = t;
    __syncthreads();
    for (int k = 2; k <= 512; k <<= 1) {
        for (int j = k >> 1; j > 0; j >>= 1) {
            int ixj = t ^ j;
            if (ixj > t) {
                float v1 = sv[t], v2 = sv[ixj];
                int   i1 = si[t], i2 = si[ixj];
                // lt(x,y): x ranks after y in descending order
                bool lt12 = (v1 < v2) || (v1 == v2 && i1 > i2);
                bool swap = ((t & k) == 0) ? lt12 : !lt12;
                if (swap) { sv[t] = v2; sv[ixj] = v1; si[t] = i2; si[ixj] = i1; }
            }
            __syncthreads();
        }
    }
    int gi = si[t];
    if (t < K_) {
        g_topidx[b*K_ + t] = gi;
        g_selmap[b*G_ + gi] = t;
    } else {
        g_selmap[b*G_ + gi] = -1;
    }
}

// ---------------- 4. gather selected group rows ----------------
__global__ void gather_kernel() {
    int bk = blockIdx.x;
    int b = bk >> 6;
    int g = g_topidx[bk];
    int d4 = threadIdx.x * 4;
    *(float4*)(g_sel + bk*D_ + d4) =
        *(const float4*)(g_groups + (b*G_ + g)*D_ + d4);
}

// ---------------- 6. attention per (b, head): 64x64, HD=64 ----------------
__global__ void attn_kernel() {
    int bh = blockIdx.x;
    int b = bh >> 4, h = bh & 15;
    __shared__ float Qs[64][65];
    __shared__ float KV[64][64];
    int t = threadIdx.x;
    const float* qbase = g_q + (b*K_)*D_ + h*HD_;
    const float* kbase = g_k + (b*K_)*D_ + h*HD_;
    const float* vbase = g_v + (b*K_)*D_ + h*HD_;
    for (int i = 0; i < 64; i++) {
        Qs[i][t] = qbase[i*D_ + t];
        KV[i][t] = kbase[i*D_ + t];
    }
    __syncthreads();
    float s[64];
#pragma unroll
    for (int j = 0; j < 64; j++) s[j] = 0.f;
    for (int d = 0; d < 64; d++) {
        float qd = Qs[t][d];
#pragma unroll
        for (int j = 0; j < 64; j++) s[j] += qd * KV[j][d];
    }
    float m = -INFINITY;
#pragma unroll
    for (int j = 0; j < 64; j++) { s[j] *= 0.125f; m = fmaxf(m, s[j]); }
    float sum = 0.f;
#pragma unroll
    for (int j = 0; j < 64; j++) { s[j] = expf(s[j] - m); sum += s[j]; }
    float inv = 1.f / sum;
    __syncthreads();
    for (int i = 0; i < 64; i++) KV[i][t] = vbase[i*D_ + t];
    __syncthreads();
    float* outrow = g_ctx + (b*K_ + t)*D_ + h*HD_;
    for (int d = 0; d < 64; d++) {
        float acc = 0.f;
#pragma unroll
        for (int j = 0; j < 64; j++) acc += s[j] * KV[j][d];
        outrow[d] = acc * inv;
    }
}

// ---------------- 8. scatter-broadcast output ----------------
__global__ void scatter_kernel(float* __restrict__ out) {
    int bg = blockIdx.x;
    int b = bg >> 9, g = bg & 511;
    int k = g_selmap[bg];
    int d4 = threadIdx.x * 4;
    float4 v = make_float4(0.f, 0.f, 0.f, 0.f);
    if (k >= 0) v = *(const float4*)(g_outg + ((b << 6) + k)*D_ + d4);
    float* dst = out + (b*S_ + g*GS_)*D_ + d4;
#pragma unroll
    for (int r = 0; r < GS_; r++) *(float4*)(dst + r*D_) = v;
}

// ---------------- launch ----------------
extern "C" void kernel_launch(void* const* d_in, const int* in_sizes, int n_in,
                              void* d_out, int out_size) {
    const float* hs  = (const float*)d_in[0];
    const float* Wq  = (const float*)d_in[1];
    const float* Wk  = (const float*)d_in[2];
    const float* Wv  = (const float*)d_in[3];
    const float* Wo  = (const float*)d_in[4];
    const float* Ws1 = (const float*)d_in[5];
    const float* bs1 = (const float*)d_in[6];
    const float* Ws2 = (const float*)d_in[7];
    const float* bs2 = (const float*)d_in[8];
    float* out = (float*)d_out;

    float *p_groups, *p_h, *p_sel, *p_q, *p_k, *p_v, *p_ctx, *p_outg;
    cudaGetSymbolAddress((void**)&p_groups, g_groups);
    cudaGetSymbolAddress((void**)&p_h,      g_h);
    cudaGetSymbolAddress((void**)&p_sel,    g_sel);
    cudaGetSymbolAddress((void**)&p_q,      g_q);
    cudaGetSymbolAddress((void**)&p_k,      g_k);
    cudaGetSymbolAddress((void**)&p_v,      g_v);
    cudaGetSymbolAddress((void**)&p_ctx,    g_ctx);
    cudaGetSymbolAddress((void**)&p_outg,   g_outg);

    pool_kernel<<<BG_, 256>>>(hs);
    // scorer hidden: [4096,1024] @ [1024,256]
    gemm_tf32_3x<<<dim3(F_/64, BG_/64, 1), 128>>>(p_groups, Ws1, Ws1, Ws1,
                                                  p_h, p_h, p_h, BG_, F_, D_);
    score_reduce<<<BG_/8, 256>>>(bs1, Ws2, bs2);
    topk_bitonic<<<B_, 512>>>();
    gather_kernel<<<BK_, 256>>>();
    // QKV fused: [512,1024] @ [1024,1024] x3 in one launch
    gemm_tf32_3x<<<dim3(D_/64, BK_/64, 3), 128>>>(p_sel, Wq, Wk, Wv,
                                                  p_q, p_k, p_v, BK_, D_, D_);
    attn_kernel<<<B_*H_, 64>>>();
    // Wo: [512,1024] @ [1024,1024]
    gemm_tf32_3x<<<dim3(D_/64, BK_/64, 1), 128>>>(p_ctx, Wo, Wo, Wo,
                                                  p_outg, p_outg, p_outg, BK_, D_, D_);
    scatter_kernel<<<BG_, 256>>>(out);
}